// round 1
// baseline (speedup 1.0000x reference)
#include <cuda_runtime.h>
#include <cstdint>

#define N_DAGS  16384
#define N_NODES 48
#define DF      62
#define NCLS    500
#define K2B     256     // pooling partial blocks (16384/64)

typedef unsigned long long ull;

// ---------------- scratch (no cudaMalloc allowed) ----------------
__device__ float g_single0[N_DAGS * 64];
__device__ float g_last   [N_DAGS * 64];
__device__ float g_score  [N_DAGS];
__device__ float g_partP  [K2B * 64];
__device__ float g_partS  [K2B];
__device__ float g_partM  [K2B];

// ---------------- packed f32x2 helpers ----------------
__device__ __forceinline__ ull ffma2(ull a, ull b, ull c) {
    ull d;
    asm("fma.rn.f32x2 %0, %1, %2, %3;" : "=l"(d) : "l"(a), "l"(b), "l"(c));
    return d;
}
__device__ __forceinline__ ull pack2(float a, float b) {
    return (ull)__float_as_uint(a) | ((ull)__float_as_uint(b) << 32);
}
__device__ __forceinline__ float lo2(ull v) { return __uint_as_float((unsigned)v); }
__device__ __forceinline__ float hi2(ull v) { return __uint_as_float((unsigned)(v >> 32)); }

// =================================================================
// K0: single0[d] = relu(W_single @ atoms[d,0,:] + b_single)
// =================================================================
__global__ void k_single0(const float* __restrict__ atoms,
                          const float* __restrict__ Ws,
                          const float* __restrict__ bs) {
    __shared__ float Wsm[DF * DF];
    __shared__ float arow[64];
    int tid = threadIdx.x;  // 64 threads
    for (int i = tid; i < DF * DF; i += 64) Wsm[i] = Ws[i];
    __syncthreads();
    for (int d = blockIdx.x; d < N_DAGS; d += gridDim.x) {
        if (tid < DF) arow[tid] = atoms[(size_t)d * N_NODES * DF + tid];
        __syncthreads();
        if (tid < DF) {
            float acc = bs[tid];
            #pragma unroll
            for (int f = 0; f < DF; f++) acc = fmaf(Wsm[tid * DF + f], arow[f], acc);
            g_single0[d * 64 + tid] = fmaxf(acc, 0.f);
        }
        __syncthreads();
    }
}

// =================================================================
// K1: recurrent DAG forward. One DAG per 128-thread block (grid-stride).
// Merge weights live in registers as packed f32x2 pairs.
// =================================================================
__global__ void __launch_bounds__(128, 4)
k_dag(const float* __restrict__ atoms, const int* __restrict__ preds,
      const float* __restrict__ Wm,   const float* __restrict__ bmerge,
      const float* __restrict__ attw, const float* __restrict__ dagw,
      const float* __restrict__ Ws,   const float* __restrict__ bs) {
    __shared__ __align__(16) float outs_sm[N_NODES * 64];
    __shared__ __align__(16) float atoms_sm[N_NODES * 64];
    __shared__ __align__(16) float xs_agg[64];
    __shared__ float parts[2][64];
    __shared__ float scores_sm[4];
    __shared__ __align__(16) int preds_sm[N_NODES * 4];

    const int tid  = threadIdx.x;
    const int lane = tid & 31;
    const int warp = tid >> 5;
    const int h    = tid >> 6;   // which 62-wide half of k
    const int g    = tid & 63;   // output index (g<62 active)

    // per-thread constants
    const float attw_lo = attw[lane];
    const float attw_hi = (lane < DF - 32) ? attw[lane + 32] : 0.f;
    const float dagw_lo = dagw[lane];
    const float dagw_hi = (lane < DF - 32) ? dagw[lane + 32] : 0.f;
    const float bm      = (g < DF) ? bmerge[g] : 0.f;

    // merge weights: pairs over local kk in [0,62), padded to 32 pairs
    ull W2[32];
    #pragma unroll
    for (int j = 0; j < 32; j++) {
        float w0 = 0.f, w1 = 0.f;
        if (g < DF && j < 31) {
            int k0 = h * DF + 2 * j;
            w0 = Wm[g * 124 + k0];
            w1 = Wm[g * 124 + k0 + 1];
        }
        W2[j] = pack2(w0, w1);
    }
    if (tid < 2) xs_agg[62 + tid] = 0.f;   // pad lanes, never overwritten

    for (int d = blockIdx.x; d < N_DAGS; d += gridDim.x) {
        // ---- preload DAG tile ----
        const float* Ad = atoms + (size_t)d * N_NODES * DF;
        for (int idx = tid; idx < N_NODES * 64; idx += 128) {
            int n = idx >> 6, c = idx & 63;
            atoms_sm[idx] = (c < DF) ? Ad[n * DF + c] : 0.f;
        }
        for (int idx = tid; idx < N_NODES * 4; idx += 128)
            preds_sm[idx] = preds[(size_t)d * N_NODES * 4 + idx];
        if (h == 0 && g < DF) outs_sm[g] = g_single0[d * 64 + g];   // t=0: always pred-less
        __syncthreads();

        for (int t = 1; t < N_NODES; t++) {
            // ---- phase 1: predecessor scores (one warp per pred slot) ----
            int pr = preds_sm[t * 4 + warp];
            float sc = -1e30f;
            if (pr >= 0) {
                float v = outs_sm[pr * 64 + lane] * attw_lo;
                if (lane < DF - 32) v = fmaf(outs_sm[pr * 64 + lane + 32], attw_hi, v);
                #pragma unroll
                for (int o = 16; o > 0; o >>= 1) v += __shfl_xor_sync(0xffffffffu, v, o);
                sc = v;
            }
            if (lane == 0) scores_sm[warp] = sc;
            __syncthreads();

            const int p0 = preds_sm[t * 4 + 0], p1 = preds_sm[t * 4 + 1];
            const int p2 = preds_sm[t * 4 + 2], p3 = preds_sm[t * 4 + 3];
            const bool v0 = p0 >= 0, v1 = p1 >= 0, v2 = p2 >= 0, v3 = p3 >= 0;
            if (!(v0 | v1 | v2 | v3)) {
                // rare: no predecessors at t>0 -> single path from gmem weights
                if (h == 0 && g < DF) {
                    float acc = bs[g];
                    for (int f = 0; f < DF; f++)
                        acc = fmaf(Ws[g * DF + f], atoms_sm[t * 64 + f], acc);
                    outs_sm[t * 64 + g] = fmaxf(acc, 0.f);
                }
                __syncthreads();
                continue;
            }

            // ---- phase 2: softmax + attention aggregate ----
            float s0 = scores_sm[0], s1 = scores_sm[1], s2 = scores_sm[2], s3 = scores_sm[3];
            float m = -1e30f;
            if (v0) m = fmaxf(m, s0);
            if (v1) m = fmaxf(m, s1);
            if (v2) m = fmaxf(m, s2);
            if (v3) m = fmaxf(m, s3);
            float e0 = v0 ? __expf(s0 - m) : 0.f;
            float e1 = v1 ? __expf(s1 - m) : 0.f;
            float e2 = v2 ? __expf(s2 - m) : 0.f;
            float e3 = v3 ? __expf(s3 - m) : 0.f;
            float inv = 1.f / (e0 + e1 + e2 + e3);
            if (h == 0 && g < DF) {
                int q0 = max(p0, 0), q1 = max(p1, 0), q2 = max(p2, 0), q3 = max(p3, 0);
                float agg = e0 * outs_sm[q0 * 64 + g];
                agg = fmaf(e1, outs_sm[q1 * 64 + g], agg);
                agg = fmaf(e2, outs_sm[q2 * 64 + g], agg);
                agg = fmaf(e3, outs_sm[q3 * 64 + g], agg);
                xs_agg[g] = agg * inv;
            }
            __syncthreads();

            // ---- phase 3: merge matvec, packed f32x2, weights in registers ----
            const ulonglong2* xb = (h == 0) ? (const ulonglong2*)xs_agg
                                            : (const ulonglong2*)(atoms_sm + t * 64);
            ull acca = 0ull, accb = 0ull;
            #pragma unroll
            for (int i = 0; i < 16; i++) {
                ulonglong2 xv = xb[i];                     // LDS.128 broadcast: 2 packed pairs
                acca = ffma2(W2[2 * i],     xv.x, acca);
                accb = ffma2(W2[2 * i + 1], xv.y, accb);
            }
            parts[h][g] = lo2(acca) + hi2(acca) + lo2(accb) + hi2(accb);
            __syncthreads();

            // ---- phase 4: combine halves, bias, relu ----
            if (h == 0 && g < DF)
                outs_sm[t * 64 + g] = fmaxf(parts[0][g] + parts[1][g] + bm, 0.f);
            __syncthreads();
        }

        // ---- finalize DAG: sink output + pooling score ----
        if (h == 0 && g < DF) g_last[(size_t)d * 64 + g] = outs_sm[47 * 64 + g];
        if (warp == 0) {
            float v = outs_sm[47 * 64 + lane] * dagw_lo;
            if (lane < DF - 32) v = fmaf(outs_sm[47 * 64 + lane + 32], dagw_hi, v);
            #pragma unroll
            for (int o = 16; o > 0; o >>= 1) v += __shfl_xor_sync(0xffffffffu, v, o);
            if (lane == 0) g_score[d] = v;
        }
        __syncthreads();
    }
}

// =================================================================
// K2: per-block partial softmax pooling over 64 DAGs (deterministic)
// =================================================================
__global__ void k_pool_partial() {
    __shared__ float sm_e[64];
    __shared__ float sm_red[4];
    int tid = threadIdx.x;        // 128
    int b = blockIdx.x;
    int d0 = b * 64;

    float s = (tid < 64) ? g_score[d0 + tid] : -1e30f;
    float v = s;
    #pragma unroll
    for (int o = 16; o > 0; o >>= 1) v = fmaxf(v, __shfl_xor_sync(0xffffffffu, v, o));
    if ((tid & 31) == 0 && tid < 64) sm_red[tid >> 5] = v;
    __syncthreads();
    float m = fmaxf(sm_red[0], sm_red[1]);

    float e = (tid < 64) ? __expf(s - m) : 0.f;
    if (tid < 64) sm_e[tid] = e;
    float se = e;
    #pragma unroll
    for (int o = 16; o > 0; o >>= 1) se += __shfl_xor_sync(0xffffffffu, se, o);
    if ((tid & 31) == 0 && tid < 64) sm_red[2 + (tid >> 5)] = se;
    __syncthreads();
    if (tid == 0) { g_partS[b] = sm_red[2] + sm_red[3]; g_partM[b] = m; }
    if (tid < DF) {
        float acc = 0.f;
        #pragma unroll 4
        for (int dd = 0; dd < 64; dd++)
            acc = fmaf(sm_e[dd], g_last[(size_t)(d0 + dd) * 64 + tid], acc);
        g_partP[b * 64 + tid] = acc;
    }
}

// =================================================================
// K3: combine partials -> pooled -> sigmoid(W_final @ pooled + b)
// =================================================================
__global__ void k_final(const float* __restrict__ Wf, const float* __restrict__ bf,
                        float* __restrict__ out) {
    __shared__ float sw[K2B];
    __shared__ float smMax[16];
    __shared__ float smSum[16];
    __shared__ float smScalar[2];
    __shared__ float pooled[DF];
    int tid = threadIdx.x;        // 512
    int lane = tid & 31, warp = tid >> 5;

    float m = (tid < K2B) ? g_partM[tid] : -1e30f;
    float v = m;
    #pragma unroll
    for (int o = 16; o > 0; o >>= 1) v = fmaxf(v, __shfl_xor_sync(0xffffffffu, v, o));
    if (lane == 0) smMax[warp] = v;
    __syncthreads();
    if (tid == 0) {
        float M = smMax[0];
        for (int w = 1; w < 16; w++) M = fmaxf(M, smMax[w]);
        smScalar[0] = M;
    }
    __syncthreads();
    float M = smScalar[0];

    float wb = (tid < K2B) ? __expf(m - M) : 0.f;
    if (tid < K2B) sw[tid] = wb;
    float ss = (tid < K2B) ? g_partS[tid] * wb : 0.f;
    #pragma unroll
    for (int o = 16; o > 0; o >>= 1) ss += __shfl_xor_sync(0xffffffffu, ss, o);
    if (lane == 0) smSum[warp] = ss;
    __syncthreads();
    if (tid == 0) {
        float S = 0.f;
        for (int w = 0; w < 16; w++) S += smSum[w];
        smScalar[1] = 1.f / S;
    }
    __syncthreads();
    float invS = smScalar[1];

    if (tid < DF) {
        float acc = 0.f;
        #pragma unroll 4
        for (int b2 = 0; b2 < K2B; b2++)
            acc = fmaf(sw[b2], g_partP[b2 * 64 + tid], acc);
        pooled[tid] = acc * invS;
    }
    __syncthreads();

    for (int o = tid; o < NCLS; o += 512) {
        float acc = bf[o];
        #pragma unroll
        for (int gg = 0; gg < DF; gg++) acc = fmaf(Wf[o * DF + gg], pooled[gg], acc);
        out[o] = 1.f / (1.f + __expf(-acc));
    }
}

// =================================================================
extern "C" void kernel_launch(void* const* d_in, const int* in_sizes, int n_in,
                              void* d_out, int out_size) {
    const float* atoms = (const float*)d_in[0];
    const int*   preds = (const int*)  d_in[1];
    const float* Ws    = (const float*)d_in[2];
    const float* bs    = (const float*)d_in[3];
    const float* Wm    = (const float*)d_in[4];
    const float* bm    = (const float*)d_in[5];
    const float* attw  = (const float*)d_in[6];
    const float* dagw  = (const float*)d_in[7];
    const float* Wf    = (const float*)d_in[8];
    const float* bf    = (const float*)d_in[9];
    float* out = (float*)d_out;

    k_single0<<<1024, 64>>>(atoms, Ws, bs);
    k_dag<<<1184, 128>>>(atoms, preds, Wm, bm, attw, dagw, Ws, bs);
    k_pool_partial<<<K2B, 128>>>();
    k_final<<<1, 512>>>(Wf, bf, out);
}